// round 9
// baseline (speedup 1.0000x reference)
#include <cuda_runtime.h>
#include <stdint.h>

#define B 8192
#define D 512
#define AM_THREADS 256
#define AM_GRID 888   /* 148 SMs x 6 resident blocks: exactly one wave */

__device__ int      g_idx_p[B];
__device__ int      g_idx_n[B];
__device__ float    g_rowloss[B];
__device__ uint32_t g_one = 1;   // opaque 1: keeps selected adds as IMAD (fma-side pipe)

// ---------------- compile-time threefry for key derivation ----------------
struct K2 { uint32_t a, b; };
constexpr uint32_t rotl_c(uint32_t x, int r) { return (x << r) | (x >> (32 - r)); }
constexpr K2 tf_c(uint32_t k0, uint32_t k1, uint32_t x0, uint32_t x1) {
    uint32_t ks2 = k0 ^ k1 ^ 0x1BD11BDAu;
    x0 += k0; x1 += k1;
    const int RA[4] = {13, 15, 26, 6};
    const int RB[4] = {17, 29, 16, 24};
    for (int i = 0; i < 4; i++) { x0 += x1; x1 = rotl_c(x1, RA[i]); x1 ^= x0; }
    x0 += k1;  x1 += ks2 + 1u;
    for (int i = 0; i < 4; i++) { x0 += x1; x1 = rotl_c(x1, RB[i]); x1 ^= x0; }
    x0 += ks2; x1 += k0 + 2u;
    for (int i = 0; i < 4; i++) { x0 += x1; x1 = rotl_c(x1, RA[i]); x1 ^= x0; }
    x0 += k0;  x1 += k1 + 3u;
    for (int i = 0; i < 4; i++) { x0 += x1; x1 = rotl_c(x1, RB[i]); x1 ^= x0; }
    x0 += k1;  x1 += ks2 + 4u;
    for (int i = 0; i < 4; i++) { x0 += x1; x1 = rotl_c(x1, RA[i]); x1 ^= x0; }
    x0 += ks2; x1 += k0 + 5u;
    return K2{x0, x1};
}

constexpr K2 KP = tf_c(0u, 42u, 0u, 0u);   // split(key(42))[0]
constexpr K2 KN = tf_c(0u, 42u, 0u, 1u);   // split(key(42))[1]
constexpr uint32_t KP0 = KP.a, KP1 = KP.b, KPS = KP0 ^ KP1 ^ 0x1BD11BDAu;
constexpr uint32_t KN0 = KN.a, KN1 = KN.b, KNS = KN0 ^ KN1 ^ 0x1BD11BDAu;

// d = a*one + c  (IMAD; 'one' is an opaque runtime 1)
#define MADD(d, a, c) asm("mad.lo.u32 %0, %1, %2, %3;" : "=r"(d) : "r"(a), "r"(one), "r"(c))
// round with the x0+=x1 add on IMAD; rotate+xor stay on alu
#define RNDM(ra) { MADD(x0, x1, x0); x1 = __funnelshift_l(x1, x1, (ra)); x1 ^= x0; }

__global__ void __launch_bounds__(AM_THREADS, 6) argmax_kernel(const int* __restrict__ labels) {
    __shared__ uint8_t slab[B];             // 8 KB
    __shared__ unsigned long long sredp[AM_THREADS / 32];
    __shared__ unsigned long long sredn[AM_THREADS / 32];

    const int tid = threadIdx.x;
    for (int i = tid; i < B; i += AM_THREADS) slab[i] = (uint8_t)labels[i];
    __syncthreads();

    const uint32_t one = g_one;

    for (int r = blockIdx.x; r < B; r += AM_GRID) {
        const uint32_t myl = slab[r];

        uint32_t bp = 0u, bn = 0u;          // packed: v[31:9] | kinv[8:4]
        uint32_t cnt = ((uint32_t)r << 13) + (uint32_t)tid;
        uint32_t kinv = 31u << 4;

        #pragma unroll 4
        for (int k = 0; k < 32; k++) {
            const uint32_t lab = slab[tid + k * AM_THREADS];
            const bool pos = (lab == myl);
            const uint32_t k0  = pos ? KP0 : KN0;
            const uint32_t k1  = pos ? KP1 : KN1;
            const uint32_t ks2 = pos ? KPS : KNS;

            uint32_t x1 = cnt + k1;                         // IADD3
            uint32_t x0 = x1 + k0;                          // round-1 add folded (IADD3)
            x1 = __funnelshift_l(x1, x1, 13); x1 ^= x0;     // round 1 rot/xor
            RNDM(15) RNDM(26) RNDM(6)
            MADD(x0, k1, x0);  x1 = x1 + ks2 + 1u;          // inj1 (x1 via 3-input IADD3)
            RNDM(17) RNDM(29) RNDM(16) RNDM(24)
            MADD(x0, ks2, x0); x1 = x1 + k0 + 2u;           // inj2
            RNDM(13) RNDM(15) RNDM(26) RNDM(6)
            MADD(x0, k0, x0);  x1 = x1 + k1 + 3u;           // inj3
            RNDM(17) RNDM(29) RNDM(16) RNDM(24)
            MADD(x0, k1, x0);  x1 = x1 + ks2 + 4u;          // inj4
            RNDM(13) RNDM(15) RNDM(26) RNDM(6)
            MADD(x0, ks2, x0); x1 = x1 + k0 + 5u;           // inj5

            const uint32_t v = (x0 ^ x1) & 0xFFFFFE00u;     // fused xor+and (LOP3)
            uint32_t packed; MADD(packed, v, kinv);          // v | kinv (low bits free)
            if (pos) bp = max(bp, packed); else bn = max(bn, packed);

            cnt  += AM_THREADS;
            kinv -= 16u;
        }

        // decode packed -> u64 (v23<<13)|(8191-col); warp+block argmax (first-index ties)
        const uint32_t tu = (uint32_t)tid;
        const uint32_t kp_ = 31u - ((bp >> 4) & 31u);
        const uint32_t kn_ = 31u - ((bn >> 4) & 31u);
        const uint32_t colp = tu + kp_ * AM_THREADS;
        const uint32_t coln = tu + kn_ * AM_THREADS;
        unsigned long long pkp =
            ((unsigned long long)(bp >> 9) << 13) | (unsigned long long)(8191u - colp);
        unsigned long long pkn =
            ((unsigned long long)(bn >> 9) << 13) | (unsigned long long)(8191u - coln);

        for (int off = 16; off > 0; off >>= 1) {
            unsigned long long o;
            o = __shfl_down_sync(0xFFFFFFFFu, pkp, off); if (o > pkp) pkp = o;
            o = __shfl_down_sync(0xFFFFFFFFu, pkn, off); if (o > pkn) pkn = o;
        }
        const int w = tid >> 5;
        if ((tid & 31) == 0) { sredp[w] = pkp; sredn[w] = pkn; }
        __syncthreads();
        if (tid == 0) {
            unsigned long long mp = sredp[0], mn = sredn[0];
            #pragma unroll
            for (int i = 1; i < AM_THREADS / 32; i++) {
                if (sredp[i] > mp) mp = sredp[i];
                if (sredn[i] > mn) mn = sredn[i];
            }
            g_idx_p[r] = 8191 - (int)(mp & 0x1FFFull);
            g_idx_n[r] = 8191 - (int)(mn & 0x1FFFull);
        }
        __syncthreads();
    }
}

// Per-row hinge: cos(a,p) - cos(a,n) + margin, clamped at 0.
__global__ void __launch_bounds__(128) loss_kernel(const float* __restrict__ pred) {
    __shared__ float sred[5][4];
    const int r = blockIdx.x;
    const int tid = threadIdx.x;
    const int ip  = g_idx_p[r];
    const int in_ = g_idx_n[r];
    const float* __restrict__ a = pred + (size_t)r   * D;
    const float* __restrict__ p = pred + (size_t)ip  * D;
    const float* __restrict__ n = pred + (size_t)in_ * D;

    float saa = 0.f, spp = 0.f, snn = 0.f, sap = 0.f, san = 0.f;
    for (int j = tid; j < D; j += 128) {
        const float av = a[j], pv = p[j], nv = n[j];
        saa += av * av; spp += pv * pv; snn += nv * nv;
        sap += av * pv; san += av * nv;
    }
    for (int off = 16; off > 0; off >>= 1) {
        saa += __shfl_down_sync(0xFFFFFFFFu, saa, off);
        spp += __shfl_down_sync(0xFFFFFFFFu, spp, off);
        snn += __shfl_down_sync(0xFFFFFFFFu, snn, off);
        sap += __shfl_down_sync(0xFFFFFFFFu, sap, off);
        san += __shfl_down_sync(0xFFFFFFFFu, san, off);
    }
    const int w = tid >> 5;
    if ((tid & 31) == 0) {
        sred[0][w] = saa; sred[1][w] = spp; sred[2][w] = snn;
        sred[3][w] = sap; sred[4][w] = san;
    }
    __syncthreads();
    if (tid == 0) {
        float t0 = 0, t1 = 0, t2 = 0, t3 = 0, t4 = 0;
        #pragma unroll
        for (int i = 0; i < 4; i++) {
            t0 += sred[0][i]; t1 += sred[1][i]; t2 += sred[2][i];
            t3 += sred[3][i]; t4 += sred[4][i];
        }
        const float na = fmaxf(sqrtf(t0), 1e-6f);
        const float np = fmaxf(sqrtf(t1), 1e-6f);
        const float nn = fmaxf(sqrtf(t2), 1e-6f);
        g_rowloss[r] = fmaxf(t3 / (na * np) - t4 / (na * nn) + 0.1f, 0.0f);
    }
}

__global__ void __launch_bounds__(1024) reduce_kernel(float* __restrict__ out) {
    __shared__ float s[1024];
    const int tid = threadIdx.x;
    const float4* rl = (const float4*)g_rowloss;
    float4 v0 = rl[tid];
    float4 v1 = rl[tid + 1024];
    s[tid] = (v0.x + v0.y) + (v0.z + v0.w) + (v1.x + v1.y) + (v1.z + v1.w);
    __syncthreads();
    for (int st = 512; st > 0; st >>= 1) {
        if (tid < st) s[tid] += s[tid + st];
        __syncthreads();
    }
    if (tid == 0) out[0] = s[0] * (1.0f / (float)B);
}

extern "C" void kernel_launch(void* const* d_in, const int* in_sizes, int n_in,
                              void* d_out, int out_size) {
    const float* pred   = (const float*)d_in[0];
    const int*   labels = (const int*)d_in[1];
    float* out = (float*)d_out;

    argmax_kernel<<<AM_GRID, AM_THREADS>>>(labels);
    loss_kernel<<<B, 128>>>(pred);
    reduce_kernel<<<1, 1024>>>(out);
}

// round 10
// speedup vs baseline: 1.1321x; 1.1321x over previous
#include <cuda_runtime.h>
#include <stdint.h>

#define B 8192
#define D 512
#define AM_THREADS 256
#define AM_GRID 1184   /* 148 SMs x 8 resident blocks, one wave */

__device__ int   g_idx_p[B];
__device__ int   g_idx_n[B];
__device__ float g_rowloss[B];
__device__ int   g_order[B];
__device__ int   g_base[16];

// ---------------- compile-time threefry for key derivation ----------------
struct K2 { uint32_t a, b; };
constexpr uint32_t rotl_c(uint32_t x, int r) { return (x << r) | (x >> (32 - r)); }
constexpr K2 tf_c(uint32_t k0, uint32_t k1, uint32_t x0, uint32_t x1) {
    uint32_t ks2 = k0 ^ k1 ^ 0x1BD11BDAu;
    x0 += k0; x1 += k1;
    const int RA[4] = {13, 15, 26, 6};
    const int RB[4] = {17, 29, 16, 24};
    for (int i = 0; i < 4; i++) { x0 += x1; x1 = rotl_c(x1, RA[i]); x1 ^= x0; }
    x0 += k1;  x1 += ks2 + 1u;
    for (int i = 0; i < 4; i++) { x0 += x1; x1 = rotl_c(x1, RB[i]); x1 ^= x0; }
    x0 += ks2; x1 += k0 + 2u;
    for (int i = 0; i < 4; i++) { x0 += x1; x1 = rotl_c(x1, RA[i]); x1 ^= x0; }
    x0 += k0;  x1 += k1 + 3u;
    for (int i = 0; i < 4; i++) { x0 += x1; x1 = rotl_c(x1, RB[i]); x1 ^= x0; }
    x0 += k1;  x1 += ks2 + 4u;
    for (int i = 0; i < 4; i++) { x0 += x1; x1 = rotl_c(x1, RA[i]); x1 ^= x0; }
    x0 += ks2; x1 += k0 + 5u;
    return K2{x0, x1};
}

constexpr K2 KPk = tf_c(0u, 42u, 0u, 0u);   // split(key(42))[0]
constexpr K2 KNk = tf_c(0u, 42u, 0u, 1u);   // split(key(42))[1]
constexpr uint32_t KP0 = KPk.a, KP1 = KPk.b, KPS = KP0 ^ KP1 ^ 0x1BD11BDAu;
constexpr uint32_t KN0 = KNk.a, KN1 = KNk.b, KNS = KN0 ^ KN1 ^ 0x1BD11BDAu;

#define TFRND(ra) { x0 += x1; x1 = __funnelshift_l(x1, x1, (ra)); x1 ^= x0; }

// Full threefry with compile-time keys; returns (y0^y1) & 0xFFFFFE00.
template <uint32_t K0, uint32_t K1, uint32_t KS>
__device__ __forceinline__ uint32_t tf_eval_imm(uint32_t cnt) {
    uint32_t x1 = cnt + K1;
    uint32_t x0 = x1 + K0;
    x1 = __funnelshift_l(x1, x1, 13); x1 ^= x0;
    TFRND(15) TFRND(26) TFRND(6)
    x0 += K1;  x1 += KS + 1u;
    TFRND(17) TFRND(29) TFRND(16) TFRND(24)
    x0 += KS;  x1 += K0 + 2u;
    TFRND(13) TFRND(15) TFRND(26) TFRND(6)
    x0 += K0;  x1 += K1 + 3u;
    TFRND(17) TFRND(29) TFRND(16) TFRND(24)
    x0 += K1;  x1 += KS + 4u;
    TFRND(13) TFRND(15) TFRND(26) TFRND(6)
    x0 += KS;  x1 += K0 + 5u;
    return (x0 ^ x1) & 0xFFFFFE00u;
}

// ---------------- stable counting sort of rows by label (14 labels) --------
__global__ void __launch_bounds__(448) order_kernel(const int* __restrict__ labels) {
    __shared__ int counts[14];
    __shared__ int base[16];
    const int w = threadIdx.x >> 5;
    const int lane = threadIdx.x & 31;

    int cnt = 0;
    for (int i = lane; i < B; i += 32) cnt += (labels[i] == w) ? 1 : 0;
    for (int off = 16; off > 0; off >>= 1) cnt += __shfl_down_sync(0xFFFFFFFFu, cnt, off);
    if (lane == 0) counts[w] = cnt;
    __syncthreads();
    if (threadIdx.x == 0) {
        int acc = 0;
        for (int l = 0; l < 14; l++) { base[l] = acc; acc += counts[l]; }
        base[14] = acc; base[15] = acc;
        for (int l = 0; l < 16; l++) g_base[l] = base[l];
    }
    __syncthreads();
    int pos = base[w];
    for (int i0 = 0; i0 < B; i0 += 32) {
        const int i = i0 + lane;
        const bool m = (labels[i] == w);
        const unsigned bal = __ballot_sync(0xFFFFFFFFu, m);
        if (m) {
            const int rank = __popc(bal & ((1u << lane) - 1u));
            g_order[pos + rank] = i;
        }
        pos += __popc(bal);
    }
}

// ---------------- argmax over gumbel-bit matrices -------------------------
__global__ void __launch_bounds__(AM_THREADS, 8) argmax_kernel(const int* __restrict__ labels) {
    __shared__ uint8_t  slab[B];     // 8 KB labels
    __shared__ uint16_t sord[B];     // 16 KB columns sorted by label
    __shared__ int      sbase[16];
    __shared__ unsigned long long sredp[AM_THREADS / 32];
    __shared__ unsigned long long sredn[AM_THREADS / 32];

    const int tid = threadIdx.x;
    for (int i = tid; i < B; i += AM_THREADS) {
        slab[i] = (uint8_t)labels[i];
        sord[i] = (uint16_t)g_order[i];
    }
    if (tid < 16) sbase[tid] = g_base[tid];
    __syncthreads();

    for (int r = blockIdx.x; r < B; r += AM_GRID) {
        const uint32_t myl = slab[r];
        const int posL = sbase[myl];
        const int posR = sbase[myl + 1];
        const uint32_t rB = (uint32_t)r << 13;

        // ---- NEG: all columns, KN keys as immediates; positives zeroed ----
        uint32_t bn = 0u;                    // packed: v[31:9] | kinv[8:4]
        {
            const uint32_t cnt0 = rB + (uint32_t)tid;
            #pragma unroll 4
            for (uint32_t k = 0; k < 32; k++) {
                const uint32_t lab = slab[tid + k * AM_THREADS];
                uint32_t v = tf_eval_imm<KN0, KN1, KNS>(cnt0 + k * AM_THREADS);
                v = (lab == myl) ? 0u : v;
                const uint32_t packed = v | ((31u - k) << 4);
                bn = max(bn, packed);
            }
        }

        // ---- POS: only same-label columns via sorted list, KP immediates ----
        uint32_t bv = 0u;       // best value
        uint32_t bc = 8191u;    // its column
        {
            const int iters = (posR - posL + (AM_THREADS - 1)) >> 8;
            int j = posL + tid;
            const int last = posR - 1;
            #pragma unroll 1
            for (int kk = 0; kk < iters; kk++) {
                const int i = (j < last) ? j : last;   // clamp tail: duplicate last col
                const uint32_t col = sord[i];
                const uint32_t v = tf_eval_imm<KP0, KP1, KPS>(rB + col);
                // per-thread sequence visits ascending col -> strict > keeps first index
                if (v > bv) { bv = v; bc = col; }
                j += AM_THREADS;
            }
        }

        // ---- merge: u64 (v23<<13)|(8191-col), warp+block argmax ----
        const uint32_t tu = (uint32_t)tid;
        const uint32_t kn_ = 31u - ((bn >> 4) & 31u);
        const uint32_t coln = tu + kn_ * AM_THREADS;
        unsigned long long pkn =
            ((unsigned long long)(bn >> 9) << 13) | (unsigned long long)(8191u - coln);
        unsigned long long pkp =
            ((unsigned long long)(bv >> 9) << 13) | (unsigned long long)(8191u - bc);

        for (int off = 16; off > 0; off >>= 1) {
            unsigned long long o;
            o = __shfl_down_sync(0xFFFFFFFFu, pkp, off); if (o > pkp) pkp = o;
            o = __shfl_down_sync(0xFFFFFFFFu, pkn, off); if (o > pkn) pkn = o;
        }
        const int w = tid >> 5;
        if ((tid & 31) == 0) { sredp[w] = pkp; sredn[w] = pkn; }
        __syncthreads();
        if (tid == 0) {
            unsigned long long mp = sredp[0], mn = sredn[0];
            #pragma unroll
            for (int i = 1; i < AM_THREADS / 32; i++) {
                if (sredp[i] > mp) mp = sredp[i];
                if (sredn[i] > mn) mn = sredn[i];
            }
            g_idx_p[r] = 8191 - (int)(mp & 0x1FFFull);
            g_idx_n[r] = 8191 - (int)(mn & 0x1FFFull);
        }
        __syncthreads();
    }
}

// Per-row hinge: cos(a,p) - cos(a,n) + margin, clamped at 0.
__global__ void __launch_bounds__(128) loss_kernel(const float* __restrict__ pred) {
    __shared__ float sred[5][4];
    const int r = blockIdx.x;
    const int tid = threadIdx.x;
    const int ip  = g_idx_p[r];
    const int in_ = g_idx_n[r];
    const float* __restrict__ a = pred + (size_t)r   * D;
    const float* __restrict__ p = pred + (size_t)ip  * D;
    const float* __restrict__ n = pred + (size_t)in_ * D;

    float saa = 0.f, spp = 0.f, snn = 0.f, sap = 0.f, san = 0.f;
    for (int j = tid; j < D; j += 128) {
        const float av = a[j], pv = p[j], nv = n[j];
        saa += av * av; spp += pv * pv; snn += nv * nv;
        sap += av * pv; san += av * nv;
    }
    for (int off = 16; off > 0; off >>= 1) {
        saa += __shfl_down_sync(0xFFFFFFFFu, saa, off);
        spp += __shfl_down_sync(0xFFFFFFFFu, spp, off);
        snn += __shfl_down_sync(0xFFFFFFFFu, snn, off);
        sap += __shfl_down_sync(0xFFFFFFFFu, sap, off);
        san += __shfl_down_sync(0xFFFFFFFFu, san, off);
    }
    const int w = tid >> 5;
    if ((tid & 31) == 0) {
        sred[0][w] = saa; sred[1][w] = spp; sred[2][w] = snn;
        sred[3][w] = sap; sred[4][w] = san;
    }
    __syncthreads();
    if (tid == 0) {
        float t0 = 0, t1 = 0, t2 = 0, t3 = 0, t4 = 0;
        #pragma unroll
        for (int i = 0; i < 4; i++) {
            t0 += sred[0][i]; t1 += sred[1][i]; t2 += sred[2][i];
            t3 += sred[3][i]; t4 += sred[4][i];
        }
        const float na = fmaxf(sqrtf(t0), 1e-6f);
        const float np = fmaxf(sqrtf(t1), 1e-6f);
        const float nn = fmaxf(sqrtf(t2), 1e-6f);
        g_rowloss[r] = fmaxf(t3 / (na * np) - t4 / (na * nn) + 0.1f, 0.0f);
    }
}

__global__ void __launch_bounds__(1024) reduce_kernel(float* __restrict__ out) {
    __shared__ float s[1024];
    const int tid = threadIdx.x;
    const float4* rl = (const float4*)g_rowloss;
    float4 v0 = rl[tid];
    float4 v1 = rl[tid + 1024];
    s[tid] = (v0.x + v0.y) + (v0.z + v0.w) + (v1.x + v1.y) + (v1.z + v1.w);
    __syncthreads();
    for (int st = 512; st > 0; st >>= 1) {
        if (tid < st) s[tid] += s[tid + st];
        __syncthreads();
    }
    if (tid == 0) out[0] = s[0] * (1.0f / (float)B);
}

extern "C" void kernel_launch(void* const* d_in, const int* in_sizes, int n_in,
                              void* d_out, int out_size) {
    const float* pred   = (const float*)d_in[0];
    const int*   labels = (const int*)d_in[1];
    float* out = (float*)d_out;

    order_kernel<<<1, 448>>>(labels);
    argmax_kernel<<<AM_GRID, AM_THREADS>>>(labels);
    loss_kernel<<<B, 128>>>(pred);
    reduce_kernel<<<1, 1024>>>(out);
}